// round 15
// baseline (speedup 1.0000x reference)
#include <cuda_runtime.h>
#include <cuda_fp16.h>
#include <cstdint>

// ============================================================================
// GaussianMLP fused — sm_103 plain target, fp16 mma.sync.m16n8k16.
// R15: R13 6-stage shape + 4-slot ring (144B rows) + wait_group 2 (3 groups in
//      flight) + streaming stores + __ldg eps. 512 thr, 4x4 warps, M32xN64.
// ============================================================================

#define NTILES 4096

__device__ __forceinline__ uint32_t smem_u32(const void* p) {
    uint32_t a;
    asm("{ .reg .u64 t; cvta.to.shared.u64 t, %1; cvt.u32.u64 %0, t; }" : "=r"(a) : "l"(p));
    return a;
}
__device__ __forceinline__ void mma16(float* c, const uint32_t* a, uint32_t b0, uint32_t b1) {
    asm volatile(
        "mma.sync.aligned.m16n8k16.row.col.f32.f16.f16.f32 "
        "{%0,%1,%2,%3},{%4,%5,%6,%7},{%8,%9},{%0,%1,%2,%3};"
        : "+f"(c[0]), "+f"(c[1]), "+f"(c[2]), "+f"(c[3])
        : "r"(a[0]), "r"(a[1]), "r"(a[2]), "r"(a[3]), "r"(b0), "r"(b1));
}
__device__ __forceinline__ void ldsm4(uint32_t* r, uint32_t addr) {
    asm volatile("ldmatrix.sync.aligned.m8n8.x4.shared.b16 {%0,%1,%2,%3}, [%4];"
                 : "=r"(r[0]), "=r"(r[1]), "=r"(r[2]), "=r"(r[3]) : "r"(addr));
}
#define CP16CG(dst, src) \
    asm volatile("cp.async.cg.shared.global [%0], [%1], 16;" :: "r"(dst), "l"(src))
#define CP_COMMIT() asm volatile("cp.async.commit_group;" ::: "memory")
#define CP_WAIT2()  asm volatile("cp.async.wait_group 2;" ::: "memory")

// ---------------- pre-converted half weights, [n][k] -------------------------
__device__ __align__(16) __half g_wemb_h[256 * 128];
// W2 interleaved at 8-col blocks: n' block 2t -> W_mean cols [8t,8t+8),
//                                 n' block 2t+1 -> W_logvar cols [8t,8t+8)
__device__ __align__(16) __half g_w2_h[256 * 256];

__global__ void prep_kernel(const float* __restrict__ We,
                            const float* __restrict__ Wm,
                            const float* __restrict__ Wl) {
    int i = blockIdx.x * 256 + threadIdx.x;
    if (i < 32768) {
        int n = i >> 7, k = i & 127;
        g_wemb_h[i] = __float2half(We[k * 256 + n]);
    } else if (i < 98304) {
        int j = i - 32768;
        int np = j >> 8, k = j & 255;
        int c = ((np >> 4) << 3) | (np & 7);
        float v = ((np >> 3) & 1) ? Wl[k * 128 + c] : Wm[k * 128 + c];
        g_w2_h[j] = __float2half(v);
    }
}

// ---------------- SMEM map (217088 B) ----------------------------------------
// hs   : h half tile [128][528B rows]             67584
//        (x chunks overlaid: 2 x [128][144B] = 36864, live only during L1)
// ring : 4 x 36864  W chunks [256][144B rows] (128B data + 16 pad)
// bias : 2048
#define HS_OFF    0u
#define XS0_OFF   0u
#define XS1_OFF   18432u
#define RING_OFF  67584u
#define SLOT_SZ   36864u
#define SBE_OFF   215040u
#define SBM_OFF   216064u
#define SBL_OFF   216576u
#define SMEM_TOTAL 217088
#define HS_SB 528u        // h row stride (bytes)
#define XW_SB 144u        // ring / x-chunk row stride (bytes)

__global__ void __launch_bounds__(512, 1)
gauss_kernel(const float* __restrict__ x, const float* __restrict__ eps,
             const float* __restrict__ be, const float* __restrict__ bm,
             const float* __restrict__ bl, float* __restrict__ out) {
    extern __shared__ char smem[];
    const uint32_t sm = smem_u32(smem);
    float* sbe = (float*)(smem + SBE_OFF);
    float* sbm = (float*)(smem + SBM_OFF);
    float* sbl = (float*)(smem + SBL_OFF);

    const int tid  = threadIdx.x;
    const int wid  = tid >> 5, lane = tid & 31;
    const int g    = lane >> 2, tg = lane & 3;
    const int mw   = wid & 3;                 // M block (32 rows)
    const int nw   = wid >> 2;                // N block (64 n'-cols)
    const int nb   = nw * 64;
    const size_t tile = blockIdx.x;

    const int fr_row = lane & 15;
    const uint32_t fr_kb = (lane & 16) ? 16u : 0u;   // k byte offset

    if (tid < 256) sbe[tid] = be[tid];
    if (tid < 128) { sbm[tid] = bm[tid]; sbl[tid] = bl[tid]; }

    const float* xg = x + tile * 16384;

    // ---- stage issuer: K=64 weight chunk -> ring slot (one commit, ALWAYS) --
    auto issue_stage = [&](int i) {
        if (i < 6) {
            uint32_t base = sm + RING_OFF + (uint32_t)(i & 3) * SLOT_SZ;
            const __half* w = (i < 2) ? (g_wemb_h + i * 64) : (g_w2_h + (i - 2) * 64);
            const int rs = (i < 2) ? 128 : 256;
            const int row = tid >> 1, h = tid & 1;   // 256 rows x 2 thr
            const __half* src = w + row * rs + h * 32;
            uint32_t dst = base + (uint32_t)row * XW_SB + (uint32_t)(h * 64);
            CP16CG(dst,       src);
            CP16CG(dst + 16u, src + 8);
            CP16CG(dst + 32u, src + 16);
            CP16CG(dst + 48u, src + 24);
        }
        CP_COMMIT();                                 // empty group past stage 5
    };
    // x chunk staging: LDG fp32 -> half -> STS (144B rows)
    const int x_row = tid >> 2, x_q = tid & 3;       // 128 rows x 4 thr
    float4 xr[4];
    auto ldg_x = [&](int s) {
        const float4* p = (const float4*)(xg + x_row * 128 + s * 64 + x_q * 16);
        xr[0] = p[0]; xr[1] = p[1]; xr[2] = p[2]; xr[3] = p[3];
    };
    auto sts_x = [&](int s) {
        uint4 u0, u1;
        {
            __half2 h0 = __floats2half2_rn(xr[0].x, xr[0].y);
            __half2 h1 = __floats2half2_rn(xr[0].z, xr[0].w);
            __half2 h2 = __floats2half2_rn(xr[1].x, xr[1].y);
            __half2 h3 = __floats2half2_rn(xr[1].z, xr[1].w);
            u0.x = *(uint32_t*)&h0; u0.y = *(uint32_t*)&h1;
            u0.z = *(uint32_t*)&h2; u0.w = *(uint32_t*)&h3;
        }
        {
            __half2 h0 = __floats2half2_rn(xr[2].x, xr[2].y);
            __half2 h1 = __floats2half2_rn(xr[2].z, xr[2].w);
            __half2 h2 = __floats2half2_rn(xr[3].x, xr[3].y);
            __half2 h3 = __floats2half2_rn(xr[3].z, xr[3].w);
            u1.x = *(uint32_t*)&h0; u1.y = *(uint32_t*)&h1;
            u1.z = *(uint32_t*)&h2; u1.w = *(uint32_t*)&h3;
        }
        uint32_t base = (XS0_OFF + (uint32_t)(s & 1) * 18432u)
                      + (uint32_t)x_row * XW_SB + (uint32_t)(x_q * 32);
        *(uint4*)(smem + base)       = u0;
        *(uint4*)(smem + base + 16u) = u1;
    };

    float acc[2][8][4];
    #pragma unroll
    for (int m = 0; m < 2; m++)
        #pragma unroll
        for (int n = 0; n < 8; n++)
            #pragma unroll
            for (int c = 0; c < 4; c++) acc[m][n][c] = 0.0f;

    // prologue: 3 weight groups in flight; x chunk 0 staged, chunk 1 in regs
    issue_stage(0);
    issue_stage(1);
    issue_stage(2);
    ldg_x(0); sts_x(0);
    ldg_x(1);

    // ======================= layer 1 (stages 0..1, K=64) =====================
    #pragma unroll 1
    for (int s = 0; s < 2; s++) {
        CP_WAIT2();                  // group s complete (s+1, s+2 may pend)
        __syncthreads();             // W[s] + x[s] visible; slot s-1 free
        issue_stage(s + 3);
        if (s == 0) sts_x(1);

        const uint32_t a_base = sm + (XS0_OFF + (uint32_t)(s & 1) * 18432u)
            + (uint32_t)(mw * 32 + fr_row) * XW_SB + fr_kb;
        const uint32_t b_base = sm + RING_OFF + (uint32_t)(s & 3) * SLOT_SZ
            + (uint32_t)(nb + fr_row) * XW_SB + fr_kb;
        #pragma unroll
        for (int kk = 0; kk < 4; kk++) {
            uint32_t A0[4], A1[4];
            ldsm4(A0, a_base + (uint32_t)(kk * 32));
            ldsm4(A1, a_base + 16u * XW_SB + (uint32_t)(kk * 32));
            #pragma unroll
            for (int q = 0; q < 4; q++) {
                uint32_t B[4];
                ldsm4(B, b_base + (uint32_t)(q * 16) * XW_SB + (uint32_t)(kk * 32));
                mma16(acc[0][2 * q],     A0, B[0], B[2]);
                mma16(acc[0][2 * q + 1], A0, B[1], B[3]);
                mma16(acc[1][2 * q],     A1, B[0], B[2]);
                mma16(acc[1][2 * q + 1], A1, B[1], B[3]);
            }
        }
    }
    __syncthreads();                 // all x reads done -> hs writable

    // ---- h = half(relu(acc + b_emb)) -> hs ----
    {
        #pragma unroll
        for (int m = 0; m < 2; m++) {
            const int r0 = mw * 32 + m * 16 + g;
            #pragma unroll
            for (int n = 0; n < 8; n++) {
                int col = nb + n * 8 + 2 * tg;
                float b0v = sbe[col], b1v = sbe[col + 1];
                __half2 v0 = __floats2half2_rn(fmaxf(acc[m][n][0] + b0v, 0.0f),
                                               fmaxf(acc[m][n][1] + b1v, 0.0f));
                __half2 v1 = __floats2half2_rn(fmaxf(acc[m][n][2] + b0v, 0.0f),
                                               fmaxf(acc[m][n][3] + b1v, 0.0f));
                *(__half2*)(smem + HS_OFF + (uint32_t)r0 * HS_SB + (uint32_t)(col * 2))       = v0;
                *(__half2*)(smem + HS_OFF + (uint32_t)(r0 + 8) * HS_SB + (uint32_t)(col * 2)) = v1;
            }
        }
    }
    #pragma unroll
    for (int m = 0; m < 2; m++)
        #pragma unroll
        for (int n = 0; n < 8; n++)
            #pragma unroll
            for (int c = 0; c < 4; c++) acc[m][n][c] = 0.0f;

    // ======================= layer 2 (stages 2..5, K=64) =====================
    #pragma unroll 1
    for (int s = 2; s < 6; s++) {
        CP_WAIT2();                  // group s complete
        __syncthreads();             // W[s] + (s==2: h tile) visible
        issue_stage(s + 3);          // empty commits for s+3 >= 6

        const uint32_t a_base = sm + HS_OFF
            + (uint32_t)(mw * 32 + fr_row) * HS_SB + (uint32_t)((s - 2) * 128) + fr_kb;
        const uint32_t b_base = sm + RING_OFF + (uint32_t)(s & 3) * SLOT_SZ
            + (uint32_t)(nb + fr_row) * XW_SB + fr_kb;
        #pragma unroll
        for (int kk = 0; kk < 4; kk++) {
            uint32_t A0[4], A1[4];
            ldsm4(A0, a_base + (uint32_t)(kk * 32));
            ldsm4(A1, a_base + 16u * HS_SB + (uint32_t)(kk * 32));
            #pragma unroll
            for (int q = 0; q < 4; q++) {
                uint32_t B[4];
                ldsm4(B, b_base + (uint32_t)(q * 16) * XW_SB + (uint32_t)(kk * 32));
                mma16(acc[0][2 * q],     A0, B[0], B[2]);
                mma16(acc[0][2 * q + 1], A0, B[1], B[3]);
                mma16(acc[1][2 * q],     A1, B[0], B[2]);
                mma16(acc[1][2 * q + 1], A1, B[1], B[3]);
            }
        }
    }

    // ====== epilogue: register-only (interleaved W2 pairs mean/logvar) =======
    {
        const float* eg = eps + tile * 16384;
        float* oz = out + tile * 16384;
        float* om = out + 67108864ull + tile * 16384;
        float* ol = out + 134217728ull + tile * 16384;
        #pragma unroll
        for (int m = 0; m < 2; m++) {
            const int rA = mw * 32 + m * 16 + g, rB = rA + 8;
            float2 eA[4], eB[4];
            #pragma unroll
            for (int e = 0; e < 4; e++) {
                const int c = 8 * (4 * nw + e) + 2 * tg;
                eA[e] = __ldg((const float2*)&eg[rA * 128 + c]);
                eB[e] = __ldg((const float2*)&eg[rB * 128 + c]);
            }
            #pragma unroll
            for (int e = 0; e < 4; e++) {
                const int c = 8 * (4 * nw + e) + 2 * tg;
                float bm0 = sbm[c], bm1 = sbm[c + 1];
                float bl0 = sbl[c], bl1 = sbl[c + 1];
                float me0 = acc[m][2 * e][0] + bm0, me1 = acc[m][2 * e][1] + bm1;
                float me2 = acc[m][2 * e][2] + bm0, me3 = acc[m][2 * e][3] + bm1;
                float lv0 = acc[m][2 * e + 1][0] + bl0, lv1 = acc[m][2 * e + 1][1] + bl1;
                float lv2 = acc[m][2 * e + 1][2] + bl0, lv3 = acc[m][2 * e + 1][3] + bl1;
                float2 z0, z1;
                z0.x = fmaf(__expf(0.5f * lv0), eA[e].x, me0);
                z0.y = fmaf(__expf(0.5f * lv1), eA[e].y, me1);
                z1.x = fmaf(__expf(0.5f * lv2), eB[e].x, me2);
                z1.y = fmaf(__expf(0.5f * lv3), eB[e].y, me3);
                __stcs((float2*)&oz[rA * 128 + c], z0);
                __stcs((float2*)&oz[rB * 128 + c], z1);
                __stcs((float2*)&om[rA * 128 + c], make_float2(me0, me1));
                __stcs((float2*)&om[rB * 128 + c], make_float2(me2, me3));
                __stcs((float2*)&ol[rA * 128 + c], make_float2(lv0, lv1));
                __stcs((float2*)&ol[rB * 128 + c], make_float2(lv2, lv3));
            }
        }
    }
}

// ---------------------------------------------------------------------------

extern "C" void kernel_launch(void* const* d_in, const int* in_sizes, int n_in,
                              void* d_out, int out_size) {
    const float* x   = (const float*)d_in[0];
    const float* eps = (const float*)d_in[1];
    const float* We  = (const float*)d_in[2];
    const float* be  = (const float*)d_in[3];
    const float* Wm  = (const float*)d_in[4];
    const float* bm  = (const float*)d_in[5];
    const float* Wl  = (const float*)d_in[6];
    const float* bl  = (const float*)d_in[7];
    float* out = (float*)d_out;

    cudaFuncSetAttribute(gauss_kernel, cudaFuncAttributeMaxDynamicSharedMemorySize, SMEM_TOTAL);
    prep_kernel<<<384, 256>>>(We, Wm, Wl);
    gauss_kernel<<<NTILES, 512, SMEM_TOTAL>>>(x, eps, be, bm, bl, out);
}

// round 16
// speedup vs baseline: 1.7209x; 1.7209x over previous
#include <cuda_runtime.h>
#include <cuda_fp16.h>
#include <cstdint>

// ============================================================================
// GaussianMLP fused — sm_103 plain target, fp16 mma.sync.m16n8k16.
// R16: R13 base (512 thr, 4x4 warps, M32xN64, K=64 stages) with W staging
//      privatized per nw-group (4 warps): per-group double buffers + named
//      barriers for L2 stages 3..5. Block barriers 7 -> 4.
// ============================================================================

#define NTILES 4096

__device__ __forceinline__ uint32_t smem_u32(const void* p) {
    uint32_t a;
    asm("{ .reg .u64 t; cvta.to.shared.u64 t, %1; cvt.u32.u64 %0, t; }" : "=r"(a) : "l"(p));
    return a;
}
__device__ __forceinline__ void mma16(float* c, const uint32_t* a, uint32_t b0, uint32_t b1) {
    asm volatile(
        "mma.sync.aligned.m16n8k16.row.col.f32.f16.f16.f32 "
        "{%0,%1,%2,%3},{%4,%5,%6,%7},{%8,%9},{%0,%1,%2,%3};"
        : "+f"(c[0]), "+f"(c[1]), "+f"(c[2]), "+f"(c[3])
        : "r"(a[0]), "r"(a[1]), "r"(a[2]), "r"(a[3]), "r"(b0), "r"(b1));
}
__device__ __forceinline__ void ldsm4(uint32_t* r, uint32_t addr) {
    asm volatile("ldmatrix.sync.aligned.m8n8.x4.shared.b16 {%0,%1,%2,%3}, [%4];"
                 : "=r"(r[0]), "=r"(r[1]), "=r"(r[2]), "=r"(r[3]) : "r"(addr));
}
#define CP16CG(dst, src) \
    asm volatile("cp.async.cg.shared.global [%0], [%1], 16;" :: "r"(dst), "l"(src))
#define CP_COMMIT() asm volatile("cp.async.commit_group;" ::: "memory")
#define CP_WAIT0()  asm volatile("cp.async.wait_group 0;" ::: "memory")
#define GROUP_BAR(id) asm volatile("bar.sync %0, %1;" :: "r"(id), "r"(128) : "memory")

// ---------------- pre-converted half weights, [n][k] -------------------------
__device__ __align__(16) __half g_wemb_h[256 * 128];
// W2 interleaved at 8-col blocks: n' block 2t -> W_mean cols [8t,8t+8),
//                                 n' block 2t+1 -> W_logvar cols [8t,8t+8)
__device__ __align__(16) __half g_w2_h[256 * 256];

__global__ void prep_kernel(const float* __restrict__ We,
                            const float* __restrict__ Wm,
                            const float* __restrict__ Wl) {
    int i = blockIdx.x * 256 + threadIdx.x;
    if (i < 32768) {
        int n = i >> 7, k = i & 127;
        g_wemb_h[i] = __float2half(We[k * 256 + n]);
    } else if (i < 98304) {
        int j = i - 32768;
        int np = j >> 8, k = j & 255;
        int c = ((np >> 4) << 3) | (np & 7);
        float v = ((np >> 3) & 1) ? Wl[k * 128 + c] : Wm[k * 128 + c];
        g_w2_h[j] = __float2half(v);
    }
}

// ---------------- SMEM map (159744 B) ----------------------------------------
// hs   : h half tile [128][528B rows]             67584
//        (x chunks overlaid: 2 x [128][176B] = 45056, live only during L1)
// wbuf : 4 groups x 2 parities x [64 rows][176B] = 90112
// bias : 2048
#define HS_OFF    0u
#define XS0_OFF   0u
#define XS1_OFF   22528u
#define RING_OFF  67584u
#define GRP_SZ    22528u          // per-group: 2 x 11264
#define BUF_SZ    11264u          // 64 rows x 176 B
#define SBE_OFF   157696u
#define SBM_OFF   158720u
#define SBL_OFF   159232u
#define SMEM_TOTAL 159744
#define HS_SB 528u        // h row stride (bytes)
#define XW_SB 176u        // x-chunk / wbuf row stride (bytes)

__global__ void __launch_bounds__(512, 1)
gauss_kernel(const float* __restrict__ x, const float* __restrict__ eps,
             const float* __restrict__ be, const float* __restrict__ bm,
             const float* __restrict__ bl, float* __restrict__ out) {
    extern __shared__ char smem[];
    const uint32_t sm = smem_u32(smem);
    float* sbe = (float*)(smem + SBE_OFF);
    float* sbm = (float*)(smem + SBM_OFF);
    float* sbl = (float*)(smem + SBL_OFF);

    const int tid  = threadIdx.x;
    const int wid  = tid >> 5, lane = tid & 31;
    const int g    = lane >> 2, tg = lane & 3;
    const int mw   = wid & 3;                 // M block (32 rows)
    const int nw   = wid >> 2;                // N block (64 n'-cols)
    const int nb   = nw * 64;
    const size_t tile = blockIdx.x;

    const int fr_row = lane & 15;
    const uint32_t fr_kb = (lane & 16) ? 16u : 0u;   // k byte offset

    if (tid < 256) sbe[tid] = be[tid];
    if (tid < 128) { sbm[tid] = bm[tid]; sbl[tid] = bl[tid]; }

    const float* xg = x + tile * 16384;
    const uint32_t grp_base = sm + RING_OFF + (uint32_t)nw * GRP_SZ;

    // ---- group-private W stage issuer: stage i -> parity i&1 ----------------
    // Each 128-thread group stages ITS OWN 64 W-rows [nb, nb+64) of chunk i.
    auto issue_w = [&](int i) {
        if (i >= 6) return;
        const __half* w;
        int rs;
        if (i < 2) { w = g_wemb_h + i * 64; rs = 128; }
        else       { w = g_w2_h + (i - 2) * 64; rs = 256; }
        const int l = tid & 127;
        const int row = l >> 1, hh = l & 1;          // 64 rows x 2 thr
        const __half* src = w + (size_t)(nb + row) * rs + hh * 32;
        uint32_t dst = grp_base + (uint32_t)(i & 1) * BUF_SZ
                     + (uint32_t)row * XW_SB + (uint32_t)(hh * 64);
        CP16CG(dst,       src);
        CP16CG(dst + 16u, src + 8);
        CP16CG(dst + 32u, src + 16);
        CP16CG(dst + 48u, src + 24);
        CP_COMMIT();
    };
    // x chunk staging: LDG fp32 -> half -> STS (176B rows)
    const int x_row = tid >> 2, x_q = tid & 3;       // 128 rows x 4 thr
    float4 xr[4];
    auto ldg_x = [&](int s) {
        const float4* p = (const float4*)(xg + x_row * 128 + s * 64 + x_q * 16);
        xr[0] = p[0]; xr[1] = p[1]; xr[2] = p[2]; xr[3] = p[3];
    };
    auto sts_x = [&](int s) {
        uint4 u0, u1;
        {
            __half2 h0 = __floats2half2_rn(xr[0].x, xr[0].y);
            __half2 h1 = __floats2half2_rn(xr[0].z, xr[0].w);
            __half2 h2 = __floats2half2_rn(xr[1].x, xr[1].y);
            __half2 h3 = __floats2half2_rn(xr[1].z, xr[1].w);
            u0.x = *(uint32_t*)&h0; u0.y = *(uint32_t*)&h1;
            u0.z = *(uint32_t*)&h2; u0.w = *(uint32_t*)&h3;
        }
        {
            __half2 h0 = __floats2half2_rn(xr[2].x, xr[2].y);
            __half2 h1 = __floats2half2_rn(xr[2].z, xr[2].w);
            __half2 h2 = __floats2half2_rn(xr[3].x, xr[3].y);
            __half2 h3 = __floats2half2_rn(xr[3].z, xr[3].w);
            u1.x = *(uint32_t*)&h0; u1.y = *(uint32_t*)&h1;
            u1.z = *(uint32_t*)&h2; u1.w = *(uint32_t*)&h3;
        }
        uint32_t base = (XS0_OFF + (uint32_t)(s & 1) * 22528u)
                      + (uint32_t)x_row * XW_SB + (uint32_t)(x_q * 32);
        *(uint4*)(smem + base)       = u0;
        *(uint4*)(smem + base + 16u) = u1;
    };

    float acc[2][8][4];
    #pragma unroll
    for (int m = 0; m < 2; m++)
        #pragma unroll
        for (int n = 0; n < 8; n++)
            #pragma unroll
            for (int c = 0; c < 4; c++) acc[m][n][c] = 0.0f;

    // W B-fragment base for a given parity (group-local rows)
    auto wb_base = [&](int parity) -> uint32_t {
        return grp_base + (uint32_t)parity * BUF_SZ
             + (uint32_t)fr_row * XW_SB + fr_kb;
    };
    // one K=64 compute block (layer 1: A from x buffer xb)
    auto l1_block = [&](uint32_t a_base, uint32_t b_base) {
        #pragma unroll
        for (int kk = 0; kk < 4; kk++) {
            uint32_t A0[4], A1[4];
            ldsm4(A0, a_base + (uint32_t)(kk * 32));
            ldsm4(A1, a_base + 16u * XW_SB + (uint32_t)(kk * 32));
            #pragma unroll
            for (int q = 0; q < 4; q++) {
                uint32_t B[4];
                ldsm4(B, b_base + (uint32_t)(q * 16) * XW_SB + (uint32_t)(kk * 32));
                mma16(acc[0][2 * q],     A0, B[0], B[2]);
                mma16(acc[0][2 * q + 1], A0, B[1], B[3]);
                mma16(acc[1][2 * q],     A1, B[0], B[2]);
                mma16(acc[1][2 * q + 1], A1, B[1], B[3]);
            }
        }
    };
    auto l2_block = [&](int c32, uint32_t b_base) {
        const uint32_t a_base = sm + HS_OFF
            + (uint32_t)(mw * 32 + fr_row) * HS_SB + (uint32_t)(c32 * 128) + fr_kb;
        #pragma unroll
        for (int kk = 0; kk < 4; kk++) {
            uint32_t A0[4], A1[4];
            ldsm4(A0, a_base + (uint32_t)(kk * 32));
            ldsm4(A1, a_base + 16u * HS_SB + (uint32_t)(kk * 32));
            #pragma unroll
            for (int q = 0; q < 4; q++) {
                uint32_t B[4];
                ldsm4(B, b_base + (uint32_t)(q * 16) * XW_SB + (uint32_t)(kk * 32));
                mma16(acc[0][2 * q],     A0, B[0], B[2]);
                mma16(acc[0][2 * q + 1], A0, B[1], B[3]);
                mma16(acc[1][2 * q],     A1, B[0], B[2]);
                mma16(acc[1][2 * q + 1], A1, B[1], B[3]);
            }
        }
    };

    // ---- prologue: stage 0 in flight; x chunk 0 staged, chunk 1 in regs -----
    issue_w(0);
    ldg_x(0); sts_x(0);
    ldg_x(1);

    // ======================= layer 1 (stages 0..1) ===========================
    CP_WAIT0();
    __syncthreads();                 // barrier 1: W0 + x0 visible
    issue_w(1);
    sts_x(1);
    l1_block(sm + XS0_OFF + (uint32_t)(mw * 32 + fr_row) * XW_SB + fr_kb, wb_base(0));

    CP_WAIT0();
    __syncthreads();                 // barrier 2: W1 + x1 visible; par0 free
    issue_w(2);
    l1_block(sm + XS1_OFF + (uint32_t)(mw * 32 + fr_row) * XW_SB + fr_kb, wb_base(1));

    __syncthreads();                 // barrier 3: all x reads done -> hs writable

    // ---- h = half(relu(acc + b_emb)) -> hs ----
    {
        #pragma unroll
        for (int m = 0; m < 2; m++) {
            const int r0 = mw * 32 + m * 16 + g;
            #pragma unroll
            for (int n = 0; n < 8; n++) {
                int col = nb + n * 8 + 2 * tg;
                float b0v = sbe[col], b1v = sbe[col + 1];
                __half2 v0 = __floats2half2_rn(fmaxf(acc[m][n][0] + b0v, 0.0f),
                                               fmaxf(acc[m][n][1] + b1v, 0.0f));
                __half2 v1 = __floats2half2_rn(fmaxf(acc[m][n][2] + b0v, 0.0f),
                                               fmaxf(acc[m][n][3] + b1v, 0.0f));
                *(__half2*)(smem + HS_OFF + (uint32_t)r0 * HS_SB + (uint32_t)(col * 2))       = v0;
                *(__half2*)(smem + HS_OFF + (uint32_t)(r0 + 8) * HS_SB + (uint32_t)(col * 2)) = v1;
            }
        }
    }
    #pragma unroll
    for (int m = 0; m < 2; m++)
        #pragma unroll
        for (int n = 0; n < 8; n++)
            #pragma unroll
            for (int c = 0; c < 4; c++) acc[m][n][c] = 0.0f;

    CP_WAIT0();                      // W chunk 2 (issued before barrier 2) done
    __syncthreads();                 // barrier 4: h + W2c0 visible; par1 free

    // ======================= layer 2 (stages 2..5) ===========================
    issue_w(3);
    l2_block(0, wb_base(0));         // stage 2 (parity 0)

    #pragma unroll 1
    for (int s = 3; s < 6; s++) {
        CP_WAIT0();                  // this thread's group stage-s load done
        GROUP_BAR(1 + nw);           // group-local: stage-s visible, old buf free
        issue_w(s + 1);              // (no-op for s+1 == 6)
        l2_block(s - 2, wb_base(s & 1));
    }

    // ====== epilogue: register-only (interleaved W2 pairs mean/logvar) =======
    {
        const float* eg = eps + tile * 16384;
        float* oz = out + tile * 16384;
        float* om = out + 67108864ull + tile * 16384;
        float* ol = out + 134217728ull + tile * 16384;
        #pragma unroll
        for (int m = 0; m < 2; m++) {
            const int rA = mw * 32 + m * 16 + g, rB = rA + 8;
            float2 eA[4], eB[4];
            #pragma unroll
            for (int e = 0; e < 4; e++) {
                const int c = 8 * (4 * nw + e) + 2 * tg;
                eA[e] = *(const float2*)&eg[rA * 128 + c];
                eB[e] = *(const float2*)&eg[rB * 128 + c];
            }
            #pragma unroll
            for (int e = 0; e < 4; e++) {
                const int c = 8 * (4 * nw + e) + 2 * tg;
                float bm0 = sbm[c], bm1 = sbm[c + 1];
                float bl0 = sbl[c], bl1 = sbl[c + 1];
                float me0 = acc[m][2 * e][0] + bm0, me1 = acc[m][2 * e][1] + bm1;
                float me2 = acc[m][2 * e][2] + bm0, me3 = acc[m][2 * e][3] + bm1;
                float lv0 = acc[m][2 * e + 1][0] + bl0, lv1 = acc[m][2 * e + 1][1] + bl1;
                float lv2 = acc[m][2 * e + 1][2] + bl0, lv3 = acc[m][2 * e + 1][3] + bl1;
                float2 z0, z1;
                z0.x = fmaf(__expf(0.5f * lv0), eA[e].x, me0);
                z0.y = fmaf(__expf(0.5f * lv1), eA[e].y, me1);
                z1.x = fmaf(__expf(0.5f * lv2), eB[e].x, me2);
                z1.y = fmaf(__expf(0.5f * lv3), eB[e].y, me3);
                *(float2*)&oz[rA * 128 + c] = z0;
                *(float2*)&oz[rB * 128 + c] = z1;
                *(float2*)&om[rA * 128 + c] = make_float2(me0, me1);
                *(float2*)&om[rB * 128 + c] = make_float2(me2, me3);
                *(float2*)&ol[rA * 128 + c] = make_float2(lv0, lv1);
                *(float2*)&ol[rB * 128 + c] = make_float2(lv2, lv3);
            }
        }
    }
}

// ---------------------------------------------------------------------------

extern "C" void kernel_launch(void* const* d_in, const int* in_sizes, int n_in,
                              void* d_out, int out_size) {
    const float* x   = (const float*)d_in[0];
    const float* eps = (const float*)d_in[1];
    const float* We  = (const float*)d_in[2];
    const float* be  = (const float*)d_in[3];
    const float* Wm  = (const float*)d_in[4];
    const float* bm  = (const float*)d_in[5];
    const float* Wl  = (const float*)d_in[6];
    const float* bl  = (const float*)d_in[7];
    float* out = (float*)d_out;

    cudaFuncSetAttribute(gauss_kernel, cudaFuncAttributeMaxDynamicSharedMemorySize, SMEM_TOTAL);
    prep_kernel<<<384, 256>>>(We, Wm, Wl);
    gauss_kernel<<<NTILES, 512, SMEM_TOTAL>>>(x, eps, be, bm, bl, out);
}